// round 7
// baseline (speedup 1.0000x reference)
#include <cuda_runtime.h>
#include <math.h>

#define NT 20

// layout: per image, anchors concatenated {sc0:9408, sc1:2352, sc2:588} = 12348
// idx = sc*64 + b

__device__ unsigned long long g_best[192 * NT];   // packed (iou_bits<<32)|~a ; 0 = sentinel
__device__ int   g_tickA[192];
__device__ int   g_tickB[192];
__device__ int   g_ctr;
__device__ unsigned char g_state[64][12348];      // state*32 + matched_t (0=neg,1=mid,2=pos)
__device__ unsigned int  g_keys[64][12348];       // monotone-transformed obj for negs, 0 else
__device__ float g_psums[192][4][3];              // per-chunk partial (sb, sce, sl1)
__device__ int   g_pnp[192][4], g_pnn[192][4];
__device__ float g_partial[192 * 3];

__device__ __forceinline__ float blk_sum_f(float v, float* wred, int tid) {
#pragma unroll
    for (int o = 16; o; o >>= 1) v += __shfl_down_sync(0xffffffffu, v, o);
    if ((tid & 31) == 0) wred[tid >> 5] = v;
    __syncthreads();
    float r = 0.f;
    if (tid == 0) {
#pragma unroll
        for (int i = 0; i < 8; i++) r += wred[i];
    }
    __syncthreads();
    return r;  // tid 0 only
}

__device__ __forceinline__ int blk_sum_i(int v, int* wred, int tid) {
#pragma unroll
    for (int o = 16; o; o >>= 1) v += __shfl_down_sync(0xffffffffu, v, o);
    if ((tid & 31) == 0) wred[tid >> 5] = v;
    __syncthreads();
    int r = 0;
    if (tid == 0) {
#pragma unroll
        for (int i = 0; i < 8; i++) r += wred[i];
    }
    __syncthreads();
    return r;  // tid 0 only
}

// order-preserving float -> uint (total order matching float <)
__device__ __forceinline__ unsigned key_xform(float x) {
    unsigned bits = __float_as_uint(x);
    return (bits & 0x80000000u) ? ~bits : (bits | 0x80000000u);
}
__device__ __forceinline__ float key_inv(unsigned u) {
    unsigned bits = (u & 0x80000000u) ? (u & 0x7FFFFFFFu) : ~u;
    return __uint_as_float(bits);
}
// exact softplus-style bce for y=0, reference formula
__device__ __forceinline__ float bce_neg(float x) {
    return fmaxf(x, 0.f) + log1pf(expf(-fabsf(x)));
}

// chunk mapping: blockIdx.x 0..5 -> (sc, c0, ncell, H, stride, off)
__device__ __forceinline__ void chunk_map(int chunk, int& sc, int& c0, int& ncell,
                                          int& H, float& stride, int& off) {
    if (chunk < 4)       { sc = 0; c0 = chunk * 784; ncell = 784; H = 56; stride = 8.f;  off = 0; }
    else if (chunk == 4) { sc = 1; c0 = 0;           ncell = 784; H = 28; stride = 16.f; off = 9408; }
    else                 { sc = 2; c0 = 0;           ncell = 196; H = 14; stride = 32.f; off = 11760; }
}

// ---------------- KA: IoU matching + forced matches ----------------
__global__ __launch_bounds__(256) void ka_match(const float* __restrict__ tbx) {
    __shared__ float4 s_ctb[NT];
    __shared__ float  s_car[NT];
    __shared__ int    s_cti[NT];
    __shared__ unsigned long long s_best[NT];
    __shared__ unsigned long long s_fb[NT];
    __shared__ int s_nact, s_last;

    const int tid = threadIdx.x;
    const int b = blockIdx.y;
    int sc, c0, ncell, H, off; float stride;
    chunk_map(blockIdx.x, sc, c0, ncell, H, stride, off);
    const int idx = sc * 64 + b;

    if (tid < NT) s_best[tid] = 0ull;
    if (tid < 32) {
        bool act = false; float4 tb = make_float4(0.f, 0.f, 0.f, 0.f);
        if (tid < NT) {
            tb = ((const float4*)tbx)[b * NT + tid];
            float ylo = ((float)(c0 / H) - 1.f) * stride;
            float yhi = ((float)(c0 / H + ncell / H) + 1.f) * stride;
            act = (tb.w > ylo) && (tb.y < yhi);
        }
        unsigned m = __ballot_sync(0xffffffffu, act);
        if (act) {  // order-preserving compaction (t ascending) -> deterministic ties
            int p = __popc(m & ((1u << tid) - 1));
            s_ctb[p] = tb;
            s_car[p] = (tb.z - tb.x) * (tb.w - tb.y);
            s_cti[p] = tid;
        }
        if (tid == 0) s_nact = __popc(m);
    }
    __syncthreads();
    const int nact = s_nact;
    const int iters = (ncell + 255) >> 8;

    for (int it = 0; it < iters; it++) {
        int cell = c0 + tid + (it << 8);
        bool valid = cell < c0 + ncell;
        int x = 0, y = 0; float cx = 0.f, cy = 0.f;
        if (valid) {
            x = cell % H; y = cell / H;
            cx = ((float)x + 0.5f) * stride;
            cy = ((float)y + 0.5f) * stride;
        }
#pragma unroll
        for (int k = 0; k < 3; k++) {
            float hw = (k == 0) ? stride : ((k == 1) ? 1.25f * stride : 1.5f * stride);
            float ax0 = cx - hw, ay0 = cy - hw, ax1 = cx + hw, ay1 = cy + hw;
            float areaA = (ax1 - ax0) * (ay1 - ay0);
            int a = cell * 3 + k;
            float best = 0.f; int bt = 0;
            unsigned long long na = (unsigned long long)(unsigned int)(~a);
            for (int j = 0; j < nact; j++) {
                float4 tb = s_ctb[j];
                unsigned long long pk = 0ull;
                if (valid) {
                    float iw = fminf(ax1, tb.z) - fmaxf(ax0, tb.x);
                    float ih = fminf(ay1, tb.w) - fmaxf(ay0, tb.y);
                    if (iw > 0.f && ih > 0.f) {
                        float inter = iw * ih;
                        float iou = inter / (areaA + s_car[j] - inter + 1e-9f);
                        if (iou > best) { best = iou; bt = s_cti[j]; }  // first t wins ties
                        pk = ((unsigned long long)__float_as_uint(iou) << 32) | na;
                    }
                }
                unsigned m = __ballot_sync(0xffffffffu, pk != 0ull);
                if (m) {
#pragma unroll
                    for (int o = 16; o; o >>= 1) {
                        unsigned long long w = __shfl_down_sync(0xffffffffu, pk, o);
                        if (w > pk) pk = w;
                    }
                    if ((tid & 31) == 0) atomicMax(&s_best[s_cti[j]], pk);
                }
            }
            if (valid) {
                int state = (best >= 0.5f) ? 2 : ((best < 0.3f) ? 0 : 1);
                g_state[b][off + a] = (unsigned char)(state * 32 + bt);
            }
        }
    }
    __syncthreads();
    if (tid < NT && s_best[tid] != 0ull)
        atomicMax(&g_best[idx * NT + tid], s_best[tid]);

    // per-image ticket: last chunk block applies forced matches
    __threadfence();
    if (tid == 0) {
        int nch = (sc == 0) ? 4 : 1;
        s_last = (atomicAdd(&g_tickA[idx], 1) == nch - 1);
    }
    __syncthreads();
    if (!s_last) return;
    if (tid < NT) s_fb[tid] = g_best[idx * NT + tid];
    __syncthreads();
    if (tid == 0) {
        for (int t = 0; t < NT; t++) {  // sequential: last-write-wins like .at[].set
            unsigned long long v = s_fb[t];
            unsigned int a = (v == 0ull) ? 0u : ~(unsigned int)(v & 0xFFFFFFFFull);
            g_state[b][off + a] = (unsigned char)(2 * 32 + t);
        }
        g_tickA[idx] = 0;  // reset for next replay
    }
    if (tid < NT) g_best[idx * NT + tid] = 0ull;  // reset for next replay
}

// ---------------- KB: losses + hard-negative select + finalize ----------------
__global__ __launch_bounds__(256, 3) void kb_loss(
    const float* __restrict__ p1, const float* __restrict__ p2, const float* __restrict__ p3,
    const float* __restrict__ tbx, const int* __restrict__ tlb,
    float* __restrict__ out)
{
    __shared__ float4 s_tb4[NT];
    __shared__ int    s_tlab[NT];
    __shared__ float  s_wred[8];
    __shared__ int    s_iwred[8];
    __shared__ unsigned int s_hist[256];
    __shared__ float  s_tot[3];
    __shared__ int    s_i[4];
    __shared__ unsigned int s_u[1];
    __shared__ int    s_last, s_final;

    const int tid = threadIdx.x;
    const int b = blockIdx.y;
    int sc, c0, ncell, H, off; float stride;
    chunk_map(blockIdx.x, sc, c0, ncell, H, stride, off);
    const int idx = sc * 64 + b;
    const int cid = (sc == 0) ? blockIdx.x : 0;
    const int nch = (sc == 0) ? 4 : 1;
    const float* pred = (sc == 0) ? p1 : ((sc == 1) ? p2 : p3);
    const int HW = H * H;

    if (tid < NT) {
        s_tb4[tid] = ((const float4*)tbx)[b * NT + tid];
        s_tlab[tid] = tlb[b * NT + tid];
    }
    __syncthreads();

    const float* pim = pred + (size_t)b * 24 * HW;
    float sb = 0.f, sce = 0.f, sl1 = 0.f;
    int np = 0, nn = 0;

    for (int cell = c0 + tid; cell < c0 + ncell; cell += 256) {
#pragma unroll
        for (int k = 0; k < 3; k++) {
            int a = cell * 3 + k;
            const float* pb = pim + k * 8 * HW + cell;
            float obj = __ldg(pb + 4 * HW);
            unsigned char v = g_state[b][off + a];
            int state = v >> 5;
            int t = v & 31;
            unsigned int key = 0u;
            if (state == 0) { key = key_xform(obj); nn++; }   // NO transcendental here
            g_keys[b][off + a] = key;
            if (state == 2) {
                np++;
                sb += fmaxf(obj, 0.f) - obj + log1pf(expf(-fabsf(obj)));  // y=1 bce
                float c0v = __ldg(pb + 5 * HW);
                float c1v = __ldg(pb + 6 * HW);
                float c2v = __ldg(pb + 7 * HW);
                float m = fmaxf(c0v, fmaxf(c1v, c2v));
                float lse = m + logf(expf(c0v - m) + expf(c1v - m) + expf(c2v - m));
                int lab = s_tlab[t] - 1;
                float ct = (lab == 0) ? c0v : ((lab == 1) ? c1v : c2v);
                sce += lse - ct;
                int x = cell % H, y = cell / H;
                float cx = ((float)x + 0.5f) * stride;
                float cy = ((float)y + 0.5f) * stride;
                float hw = (k == 0) ? stride : ((k == 1) ? 1.25f * stride : 1.5f * stride);
                float aw = 2.f * hw;
                float4 tb = s_tb4[t];
                float gw = tb.z - tb.x, gh = tb.w - tb.y;
                float gcx = (tb.x + tb.z) * 0.5f, gcy = (tb.y + tb.w) * 0.5f;
                float td0 = (gcx - cx) / aw;
                float td1 = (gcy - cy) / aw;
                float td2 = logf(gw / aw);
                float td3 = logf(gh / aw);
                float d;
                d = fabsf(__ldg(pb + 0 * HW) - td0); sl1 += (d < 1.f) ? 0.5f * d * d : d - 0.5f;
                d = fabsf(__ldg(pb + 1 * HW) - td1); sl1 += (d < 1.f) ? 0.5f * d * d : d - 0.5f;
                d = fabsf(__ldg(pb + 2 * HW) - td2); sl1 += (d < 1.f) ? 0.5f * d * d : d - 0.5f;
                d = fabsf(__ldg(pb + 3 * HW) - td3); sl1 += (d < 1.f) ? 0.5f * d * d : d - 0.5f;
            }
        }
    }
    __syncthreads();

    float sb_t  = blk_sum_f(sb,  s_wred, tid);
    float sce_t = blk_sum_f(sce, s_wred, tid);
    float sl1_t = blk_sum_f(sl1, s_wred, tid);
    int   np_t  = blk_sum_i(np,  s_iwred, tid);
    int   nn_t  = blk_sum_i(nn,  s_iwred, tid);
    if (tid == 0) {
        g_psums[idx][cid][0] = sb_t;
        g_psums[idx][cid][1] = sce_t;
        g_psums[idx][cid][2] = sl1_t;
        g_pnp[idx][cid] = np_t;
        g_pnn[idx][cid] = nn_t;
    }

    // per-image ticket: last chunk block runs the select + per-image losses
    __threadfence();
    if (tid == 0) s_last = (atomicAdd(&g_tickB[idx], 1) == nch - 1);
    __syncthreads();
    if (!s_last) return;

    if (tid == 0) {
        float S0 = 0.f, S1 = 0.f, S2 = 0.f; int NP = 0, NN = 0;
        for (int c = 0; c < nch; c++) {   // fixed order -> deterministic
            S0 += g_psums[idx][c][0];
            S1 += g_psums[idx][c][1];
            S2 += g_psums[idx][c][2];
            NP += g_pnp[idx][c];
            NN += g_pnn[idx][c];
        }
        s_tot[0] = S0; s_tot[1] = S1; s_tot[2] = S2;
        s_i[0] = NP; s_i[1] = NN;
        g_tickB[idx] = 0;  // reset for next replay
    }
    __syncthreads();

    const int A = (sc == 0) ? 9408 : ((sc == 1) ? 2352 : 588);
    const int num_pos = s_i[0];
    const int num_neg = s_i[1];
    int need = 3 * num_pos;
    if (need > num_neg) need = num_neg;

    float sum_sel = 0.f;
    if (need > 0) {
        if (tid == 0) { s_u[0] = 0u; s_i[2] = need; }
        __syncthreads();
#pragma unroll
        for (int pass = 0; pass < 4; pass++) {
            s_hist[tid] = 0u;
            __syncthreads();
            int shift = 24 - 8 * pass;
            unsigned int hi_mask = (pass == 0) ? 0u : (0xFFFFFFFFu << (shift + 8));
            unsigned int pfx = s_u[0];
            for (int a2 = tid; a2 < A; a2 += 256) {
                unsigned int key = g_keys[b][off + a2];
                if ((key & hi_mask) == pfx)
                    atomicAdd(&s_hist[(key >> shift) & 255], 1u);
            }
            __syncthreads();
            if (tid == 0) {
                unsigned int kk = (unsigned int)s_i[2];
                unsigned int cum = 0; int sel = 0;
                for (int d = 255; d >= 0; d--) {
                    unsigned int c = s_hist[d];
                    if (kk <= cum + c) { sel = d; kk -= cum; break; }
                    cum += c;
                }
                s_u[0] = pfx | ((unsigned int)sel << shift);
                s_i[2] = (int)kk;
            }
            __syncthreads();
        }
        unsigned int kth = s_u[0];
        float sg = 0.f; int cg = 0;
        for (int a2 = tid; a2 < A; a2 += 256) {
            unsigned int key = g_keys[b][off + a2];
            if (key > kth) { sg += bce_neg(key_inv(key)); cg++; }  // softplus only on selected
        }
        float sg_t = blk_sum_f(sg, s_wred, tid);
        int   cg_t = blk_sum_i(cg, s_iwred, tid);
        if (tid == 0) sum_sel = sg_t + (float)(need - cg_t) * bce_neg(key_inv(kth));
    }

    if (tid == 0) {
        int denom_obj = num_pos + need; if (denom_obj < 1) denom_obj = 1;
        int denom_cls = num_pos;        if (denom_cls < 1) denom_cls = 1;
        int denom_loc = 4 * num_pos;    if (denom_loc < 1) denom_loc = 1;
        g_partial[idx * 3 + 0] = (s_tot[0] + sum_sel) / (float)denom_obj;
        g_partial[idx * 3 + 1] = s_tot[1] / (float)denom_cls;
        g_partial[idx * 3 + 2] = s_tot[2] / (float)denom_loc;
    }

    // global ticket: last image block finalizes
    __threadfence();
    if (tid == 0) s_final = (atomicAdd(&g_ctr, 1) == 191);
    __syncthreads();
    if (s_final && tid < 32) {
        float o = 0.f, c = 0.f, l = 0.f;
        for (int i = tid; i < 192; i += 32) {
            o += g_partial[3 * i + 0];
            c += g_partial[3 * i + 1];
            l += g_partial[3 * i + 2];
        }
#pragma unroll
        for (int s = 16; s; s >>= 1) {
            o += __shfl_down_sync(0xffffffffu, o, s);
            c += __shfl_down_sync(0xffffffffu, c, s);
            l += __shfl_down_sync(0xffffffffu, l, s);
        }
        if (tid == 0) {
            o *= (1.f / 64.f);
            c *= (1.f / 64.f);
            l *= (1.f / 64.f);
            out[0] = o;
            out[1] = c;
            out[2] = l;
            out[3] = o + c + 2.f * l;
            g_ctr = 0;  // reset for next replay
        }
    }
}

extern "C" void kernel_launch(void* const* d_in, const int* in_sizes, int n_in,
                              void* d_out, int out_size) {
    const float* p1 = (const float*)d_in[0];
    const float* p2 = (const float*)d_in[1];
    const float* p3 = (const float*)d_in[2];
    const float* tb = (const float*)d_in[6];
    const int*   tl = (const int*)d_in[7];

    ka_match<<<dim3(6, 64), 256>>>(tb);
    kb_loss<<<dim3(6, 64), 256>>>(p1, p2, p3, tb, tl, (float*)d_out);
}

// round 12
// speedup vs baseline: 1.1441x; 1.1441x over previous
#include <cuda_runtime.h>
#include <math.h>

#define TB 1024
#define NW (TB / 32)
#define NT 20
#define AMAX 9408

__device__ float g_partial[192 * 3];
__device__ int   g_ctr = 0;

__device__ __forceinline__ float blk_sum_f(float v, float* wred, int tid) {
#pragma unroll
    for (int o = 16; o; o >>= 1) v += __shfl_down_sync(0xffffffffu, v, o);
    if ((tid & 31) == 0) wred[tid >> 5] = v;
    __syncthreads();
    float r = 0.f;
    if (tid == 0) {
#pragma unroll
        for (int i = 0; i < NW; i++) r += wred[i];
    }
    __syncthreads();
    return r;  // tid 0 only
}

__device__ __forceinline__ int blk_sum_i(int v, int* wred, int tid) {
#pragma unroll
    for (int o = 16; o; o >>= 1) v += __shfl_down_sync(0xffffffffu, v, o);
    if ((tid & 31) == 0) wred[tid >> 5] = v;
    __syncthreads();
    int r = 0;
    if (tid == 0) {
#pragma unroll
        for (int i = 0; i < NW; i++) r += wred[i];
    }
    __syncthreads();
    return r;  // tid 0 only
}

// order-preserving float -> uint
__device__ __forceinline__ unsigned key_xform(float x) {
    unsigned bits = __float_as_uint(x);
    return (bits & 0x80000000u) ? ~bits : (bits | 0x80000000u);
}
__device__ __forceinline__ float key_inv(unsigned u) {
    unsigned bits = (u & 0x80000000u) ? (u & 0x7FFFFFFFu) : ~u;
    return __uint_as_float(bits);
}
// exact bce for y=0 (reference formula)
__device__ __forceinline__ float bce_neg(float x) {
    return fmaxf(x, 0.f) + log1pf(expf(-fabsf(x)));
}

__global__ __launch_bounds__(TB, 1) void det_loss_kernel(
    const float* __restrict__ p1, const float* __restrict__ p2, const float* __restrict__ p3,
    const float* __restrict__ tbx, const int* __restrict__ tlb,
    float* __restrict__ out)
{
    __shared__ unsigned s_keys[AMAX];           // transformed-obj keys for negs, 0 else
    __shared__ unsigned char s_sm[AMAX];        // state*32 + matched_t
    __shared__ unsigned long long s_best[NT];   // packed (iou_bits<<32)|~a ; 0 = no overlap
    __shared__ float4 s_tb4[NT];
    __shared__ float  s_car[NT];
    __shared__ int    s_tlab[NT];
    __shared__ unsigned s_hist[256];
    __shared__ unsigned s_ws[8];
    __shared__ float s_wred[NW];
    __shared__ int   s_iwred[NW];
    __shared__ float s_f[4];
    __shared__ int   s_i[4];
    __shared__ unsigned s_u[2];
    __shared__ int   s_last;

    const int tid = threadIdx.x;
    const int b  = blockIdx.x;
    const int sc = blockIdx.y;

    const float* pred; int H, A; float stride;
    if (sc == 0)      { pred = p1; H = 56; A = 9408; stride = 8.f;  }
    else if (sc == 1) { pred = p2; H = 28; A = 2352; stride = 16.f; }
    else              { pred = p3; H = 14; A = 588;  stride = 32.f; }
    const int HW = H * H;

    if (tid < NT) {
        float4 tb = ((const float4*)tbx)[b * NT + tid];
        s_tb4[tid] = tb;
        s_car[tid] = (tb.z - tb.x) * (tb.w - tb.y);
        s_tlab[tid] = tlb[b * NT + tid];
        s_best[tid] = 0ull;   // sentinel: no overlap anywhere -> forced anchor 0
    }
    __syncthreads();

    // ---------------- Phase 1: IoU matching with warp-level target culling ----
    for (int base = 0; base < HW; base += TB) {
        int cell = base + tid;
        bool valid = cell < HW;
        // warp's cell range (lanes are consecutive cells)
        int wc0 = base + (tid & ~31);
        int wc1 = wc0 + 31; if (wc1 > HW - 1) wc1 = HW - 1;
        unsigned tmask = 0u;
        if (wc0 < HW) {
            int y0 = wc0 / H, y1 = wc1 / H;
            float ylo = ((float)y0 - 1.f) * stride;       // (y0+0.5-1.5)*stride
            float yhi = ((float)y1 + 2.f) * stride;       // (y1+0.5+1.5)*stride
            float xlo, xhi;
            if (y0 == y1) {
                int x0 = wc0 % H, x1 = wc1 % H;
                xlo = ((float)x0 - 1.f) * stride;
                xhi = ((float)x1 + 2.f) * stride;
            } else {
                xlo = -2.f * stride;
                xhi = (float)(H + 2) * stride;
            }
#pragma unroll
            for (int t = 0; t < NT; t++) {
                float4 tb = s_tb4[t];
                if (tb.x < xhi && tb.z > xlo && tb.y < yhi && tb.w > ylo)
                    tmask |= 1u << t;
            }
        }
        int x = 0, y = 0; float cx = 0.f, cy = 0.f;
        if (valid) {
            x = cell % H; y = cell / H;
            cx = ((float)x + 0.5f) * stride;
            cy = ((float)y + 0.5f) * stride;
        }
#pragma unroll
        for (int k = 0; k < 3; k++) {
            float hw = (k == 0) ? stride : ((k == 1) ? 1.25f * stride : 1.5f * stride);
            float ax0 = cx - hw, ay0 = cy - hw, ax1 = cx + hw, ay1 = cy + hw;
            float areaA = 4.f * hw * hw;
            int a = cell * 3 + k;
            float best = 0.f; int bt = 0;
            unsigned long long na = (unsigned long long)(unsigned int)(~a);
            unsigned m = tmask;                    // uniform across warp
            while (m) {
                int t = __ffs(m) - 1; m &= m - 1;  // t ascending -> first-wins ties
                float4 tb = s_tb4[t];
                unsigned long long pk = 0ull;
                if (valid) {
                    float iw = fminf(ax1, tb.z) - fmaxf(ax0, tb.x);
                    float ih = fminf(ay1, tb.w) - fmaxf(ay0, tb.y);
                    if (iw > 0.f && ih > 0.f) {
                        float inter = iw * ih;
                        float iou = inter / (areaA + s_car[t] - inter + 1e-9f);
                        if (iou > best) { best = iou; bt = t; }
                        pk = ((unsigned long long)__float_as_uint(iou) << 32) | na;
                    }
                }
                if (__any_sync(0xffffffffu, pk != 0ull)) {
#pragma unroll
                    for (int o = 16; o; o >>= 1) {
                        unsigned long long w = __shfl_down_sync(0xffffffffu, pk, o);
                        if (w > pk) pk = w;        // max iou, then smaller anchor idx
                    }
                    if ((tid & 31) == 0) atomicMax(&s_best[t], pk);
                }
            }
            if (valid) {
                int state = (best >= 0.5f) ? 2 : ((best < 0.3f) ? 0 : 1);
                s_sm[a] = (unsigned char)(state * 32 + bt);
            }
        }
    }
    __syncthreads();

    // ---------------- Phase 2: forced matches (sequential, last-write-wins) ----
    if (tid == 0) {
        for (int t = 0; t < NT; t++) {
            unsigned long long v = s_best[t];
            unsigned int a = (v == 0ull) ? 0u : ~(unsigned int)(v & 0xFFFFFFFFull);
            s_sm[a] = (unsigned char)(2 * 32 + t);
        }
    }
    __syncthreads();

    // ---------------- Phase 3: per-anchor losses (no transcendentals for negs) --
    float sb = 0.f, sce = 0.f, sl1 = 0.f;
    int np = 0, nn = 0;
    const float* pim = pred + (size_t)b * 24 * HW;

    for (int cell = tid; cell < HW; cell += TB) {
#pragma unroll
        for (int k = 0; k < 3; k++) {
            int a = cell * 3 + k;
            const float* pb = pim + k * 8 * HW + cell;
            float obj = __ldg(pb + 4 * HW);
            unsigned char v = s_sm[a];
            int state = v >> 5;
            int t = v & 31;
            unsigned key = 0u;
            if (state == 0) { key = key_xform(obj); nn++; }
            s_keys[a] = key;
            if (state == 2) {
                np++;
                sb += fmaxf(obj, 0.f) - obj + log1pf(expf(-fabsf(obj)));  // y=1 bce
                float c0v = __ldg(pb + 5 * HW);
                float c1v = __ldg(pb + 6 * HW);
                float c2v = __ldg(pb + 7 * HW);
                float mx = fmaxf(c0v, fmaxf(c1v, c2v));
                float lse = mx + logf(expf(c0v - mx) + expf(c1v - mx) + expf(c2v - mx));
                int lab = s_tlab[t] - 1;
                float ct = (lab == 0) ? c0v : ((lab == 1) ? c1v : c2v);
                sce += lse - ct;
                int x = cell % H, y = cell / H;
                float cx = ((float)x + 0.5f) * stride;
                float cy = ((float)y + 0.5f) * stride;
                float hw = (k == 0) ? stride : ((k == 1) ? 1.25f * stride : 1.5f * stride);
                float aw = 2.f * hw;
                float4 tb = s_tb4[t];
                float gw = tb.z - tb.x, gh = tb.w - tb.y;
                float gcx = (tb.x + tb.z) * 0.5f, gcy = (tb.y + tb.w) * 0.5f;
                float td0 = (gcx - cx) / aw;
                float td1 = (gcy - cy) / aw;
                float td2 = logf(gw / aw);
                float td3 = logf(gh / aw);
                float d;
                d = fabsf(__ldg(pb + 0 * HW) - td0); sl1 += (d < 1.f) ? 0.5f * d * d : d - 0.5f;
                d = fabsf(__ldg(pb + 1 * HW) - td1); sl1 += (d < 1.f) ? 0.5f * d * d : d - 0.5f;
                d = fabsf(__ldg(pb + 2 * HW) - td2); sl1 += (d < 1.f) ? 0.5f * d * d : d - 0.5f;
                d = fabsf(__ldg(pb + 3 * HW) - td3); sl1 += (d < 1.f) ? 0.5f * d * d : d - 0.5f;
            }
        }
    }
    __syncthreads();

    float sb_t  = blk_sum_f(sb,  s_wred, tid);
    float sce_t = blk_sum_f(sce, s_wred, tid);
    float sl1_t = blk_sum_f(sl1, s_wred, tid);
    int   np_t  = blk_sum_i(np,  s_iwred, tid);
    int   nn_t  = blk_sum_i(nn,  s_iwred, tid);
    if (tid == 0) {
        s_f[0] = sb_t; s_f[1] = sce_t; s_f[2] = sl1_t;
        s_i[0] = np_t; s_i[1] = nn_t;
    }
    __syncthreads();

    const int num_pos = s_i[0];
    const int num_neg = s_i[1];
    int need = 3 * num_pos;
    if (need > num_neg) need = num_neg;

    // ---------------- Phase 4: radix-select top-`need` negative keys ------------
    float sum_sel = 0.f;
    if (need > 0) {
        if (tid == 0) { s_u[0] = 0u; s_i[2] = need; }
        __syncthreads();
#pragma unroll
        for (int pass = 0; pass < 4; pass++) {
            unsigned pfx = s_u[0];
            unsigned kk = (unsigned)s_i[2];
            if (tid < 256) s_hist[tid] = 0u;
            __syncthreads();
            int shift = 24 - 8 * pass;
            unsigned hi_mask = (pass == 0) ? 0u : (0xFFFFFFFFu << (shift + 8));
            for (int a2 = tid; a2 < A; a2 += TB) {
                unsigned key = s_keys[a2];
                if ((key & hi_mask) == pfx)
                    atomicAdd(&s_hist[(key >> shift) & 255], 1u);
            }
            __syncthreads();
            // parallel suffix-cumulative select over 256 bins (descending d)
            unsigned c = 0, incl = 0; int d = 0;
            if (tid < 256) {
                d = 255 - tid;             // tid order = descending bin order
                c = s_hist[d];
                unsigned lane = tid & 31;
                incl = c;
#pragma unroll
                for (int o = 1; o < 32; o <<= 1) {
                    unsigned n = __shfl_up_sync(0xffffffffu, incl, o);
                    if (lane >= o) incl += n;
                }
                if (lane == 31) s_ws[tid >> 5] = incl;
            }
            __syncthreads();
            if (tid < 256) {
                unsigned e = incl - c;     // exclusive within warp
                int w = tid >> 5;
                for (int i = 0; i < w; i++) e += s_ws[i];
                // unique bin where cumulative crosses kk
                if (e < kk && kk <= e + c) {
                    s_u[0] = pfx | ((unsigned)d << shift);
                    s_u[1] = kk - e;
                }
            }
            __syncthreads();
            if (tid == 0) s_i[2] = (int)s_u[1];
            __syncthreads();
        }
        unsigned kth = s_u[0];
        float sg = 0.f; int cg = 0;
        for (int a2 = tid; a2 < A; a2 += TB) {
            unsigned key = s_keys[a2];
            if (key > kth) { sg += bce_neg(key_inv(key)); cg++; }  // bce only on selected
        }
        float sg_t = blk_sum_f(sg, s_wred, tid);
        int   cg_t = blk_sum_i(cg, s_iwred, tid);
        if (tid == 0) sum_sel = sg_t + (float)(need - cg_t) * bce_neg(key_inv(kth));
    }

    // ---------------- Phase 5: per-image losses ----------------
    if (tid == 0) {
        int denom_obj = num_pos + need; if (denom_obj < 1) denom_obj = 1;
        int denom_cls = num_pos;        if (denom_cls < 1) denom_cls = 1;
        int denom_loc = 4 * num_pos;    if (denom_loc < 1) denom_loc = 1;
        int idx = (sc * 64 + b) * 3;
        g_partial[idx + 0] = (s_f[0] + sum_sel) / (float)denom_obj;
        g_partial[idx + 1] = s_f[1] / (float)denom_cls;
        g_partial[idx + 2] = s_f[2] / (float)denom_loc;
    }

    // ---------------- Phase 6: last block finalizes ----------------
    __threadfence();
    if (tid == 0) {
        int ticket = atomicAdd(&g_ctr, 1);
        s_last = (ticket == 191);
    }
    __syncthreads();
    if (s_last && tid < 32) {
        float o = 0.f, c = 0.f, l = 0.f;
        for (int i = tid; i < 192; i += 32) {
            o += g_partial[3 * i + 0];
            c += g_partial[3 * i + 1];
            l += g_partial[3 * i + 2];
        }
#pragma unroll
        for (int s = 16; s; s >>= 1) {
            o += __shfl_down_sync(0xffffffffu, o, s);
            c += __shfl_down_sync(0xffffffffu, c, s);
            l += __shfl_down_sync(0xffffffffu, l, s);
        }
        if (tid == 0) {
            o *= (1.f / 64.f);
            c *= (1.f / 64.f);
            l *= (1.f / 64.f);
            out[0] = o;
            out[1] = c;
            out[2] = l;
            out[3] = o + c + 2.f * l;
            g_ctr = 0;  // reset for next graph replay
        }
    }
}

extern "C" void kernel_launch(void* const* d_in, const int* in_sizes, int n_in,
                              void* d_out, int out_size) {
    const float* p1 = (const float*)d_in[0];
    const float* p2 = (const float*)d_in[1];
    const float* p3 = (const float*)d_in[2];
    const float* tb = (const float*)d_in[6];
    const int*   tl = (const int*)d_in[7];

    dim3 grid(64, 3);
    det_loss_kernel<<<grid, TB>>>(p1, p2, p3, tb, tl, (float*)d_out);
}

// round 17
// speedup vs baseline: 2.2883x; 2.0000x over previous
#include <cuda_runtime.h>
#include <math.h>

#define TB 512
#define NW (TB / 32)
#define NT 20
#define AMAX 9408

__device__ float g_partial[192 * 3];
__device__ int   g_ctr = 0;

__device__ __forceinline__ float blk_sum_f(float v, float* wred, int tid) {
#pragma unroll
    for (int o = 16; o; o >>= 1) v += __shfl_down_sync(0xffffffffu, v, o);
    if ((tid & 31) == 0) wred[tid >> 5] = v;
    __syncthreads();
    float r = 0.f;
    if (tid == 0) {
#pragma unroll
        for (int i = 0; i < NW; i++) r += wred[i];
    }
    __syncthreads();
    return r;  // tid 0 only
}

__device__ __forceinline__ int blk_sum_i(int v, int* wred, int tid) {
#pragma unroll
    for (int o = 16; o; o >>= 1) v += __shfl_down_sync(0xffffffffu, v, o);
    if ((tid & 31) == 0) wred[tid >> 5] = v;
    __syncthreads();
    int r = 0;
    if (tid == 0) {
#pragma unroll
        for (int i = 0; i < NW; i++) r += wred[i];
    }
    __syncthreads();
    return r;  // tid 0 only
}

// order-preserving float -> uint
__device__ __forceinline__ unsigned key_xform(float x) {
    unsigned bits = __float_as_uint(x);
    return (bits & 0x80000000u) ? ~bits : (bits | 0x80000000u);
}
__device__ __forceinline__ float key_inv(unsigned u) {
    unsigned bits = (u & 0x80000000u) ? (u & 0x7FFFFFFFu) : ~u;
    return __uint_as_float(bits);
}
// exact bce for y=0 (reference formula)
__device__ __forceinline__ float bce_neg(float x) {
    return fmaxf(x, 0.f) + log1pf(expf(-fabsf(x)));
}

__global__ __launch_bounds__(TB, 2) void det_loss_kernel(
    const float* __restrict__ p1, const float* __restrict__ p2, const float* __restrict__ p3,
    const float* __restrict__ tbx, const int* __restrict__ tlb,
    float* __restrict__ out)
{
    __shared__ unsigned s_keys[AMAX];           // transformed-obj keys for negs, 0 else
    __shared__ unsigned char s_sm[AMAX];        // state*32 + matched_t
    __shared__ unsigned long long s_best[NT];   // packed (iou_bits<<32)|~a ; 0 = no overlap
    __shared__ float4 s_tb4[NT];
    __shared__ float  s_car[NT];
    __shared__ int    s_tlab[NT];
    __shared__ unsigned s_hist[256];
    __shared__ unsigned s_ws[8];
    __shared__ float s_wred[NW];
    __shared__ int   s_iwred[NW];
    __shared__ float s_f[4];
    __shared__ int   s_i[4];
    __shared__ unsigned s_u[2];
    __shared__ int   s_last;

    const int tid = threadIdx.x;
    const int b  = blockIdx.x;
    const int sc = blockIdx.y;

    const float* pred; int H, A; float stride;
    if (sc == 0)      { pred = p1; H = 56; A = 9408; stride = 8.f;  }
    else if (sc == 1) { pred = p2; H = 28; A = 2352; stride = 16.f; }
    else              { pred = p3; H = 14; A = 588;  stride = 32.f; }
    const int HW = H * H;

    if (tid < NT) {
        float4 tb = ((const float4*)tbx)[b * NT + tid];
        s_tb4[tid] = tb;
        s_car[tid] = (tb.z - tb.x) * (tb.w - tb.y);
        s_tlab[tid] = tlb[b * NT + tid];
        s_best[tid] = 0ull;   // sentinel: no overlap anywhere -> forced anchor 0
    }
    __syncthreads();

    // ---------------- Phase 1: IoU matching (concentric-anchor prefilter) ------
    const float hw0 = stride, hw1 = 1.25f * stride, hw2 = 1.5f * stride;
    for (int cell = tid; cell < HW; cell += TB) {
        int x = cell % H, y = cell / H;
        float cx = ((float)x + 0.5f) * stride;
        float cy = ((float)y + 0.5f) * stride;
        float b0 = 0.f, b1 = 0.f, b2 = 0.f;   // best iou per k
        int   t0 = 0,  t1 = 0,  t2 = 0;       // best t per k
        int a0 = cell * 3;
        for (int t = 0; t < NT; t++) {        // ascending: first-wins ties
            float4 tb = s_tb4[t];
            // prefilter with largest anchor (k=2)
            float iw2 = fminf(cx + hw2, tb.z) - fmaxf(cx - hw2, tb.x);
            float ih2 = fminf(cy + hw2, tb.w) - fmaxf(cy - hw2, tb.y);
            if (iw2 <= 0.f || ih2 <= 0.f) continue;
            float area_t = s_car[t];
            // k = 2 (reuse iw2/ih2)
            {
                float inter = iw2 * ih2;
                float iou = inter / (4.f * hw2 * hw2 + area_t - inter + 1e-9f);
                if (iou > b2) { b2 = iou; t2 = t; }
                unsigned long long pk = ((unsigned long long)__float_as_uint(iou) << 32)
                                      | (unsigned int)(~(a0 + 2));
                atomicMax(&s_best[t], pk);
            }
            // k = 0
            {
                float iw = fminf(cx + hw0, tb.z) - fmaxf(cx - hw0, tb.x);
                float ih = fminf(cy + hw0, tb.w) - fmaxf(cy - hw0, tb.y);
                if (iw > 0.f && ih > 0.f) {
                    float inter = iw * ih;
                    float iou = inter / (4.f * hw0 * hw0 + area_t - inter + 1e-9f);
                    if (iou > b0) { b0 = iou; t0 = t; }
                    unsigned long long pk = ((unsigned long long)__float_as_uint(iou) << 32)
                                          | (unsigned int)(~a0);
                    atomicMax(&s_best[t], pk);
                }
            }
            // k = 1
            {
                float iw = fminf(cx + hw1, tb.z) - fmaxf(cx - hw1, tb.x);
                float ih = fminf(cy + hw1, tb.w) - fmaxf(cy - hw1, tb.y);
                if (iw > 0.f && ih > 0.f) {
                    float inter = iw * ih;
                    float iou = inter / (4.f * hw1 * hw1 + area_t - inter + 1e-9f);
                    if (iou > b1) { b1 = iou; t1 = t; }
                    unsigned long long pk = ((unsigned long long)__float_as_uint(iou) << 32)
                                          | (unsigned int)(~(a0 + 1));
                    atomicMax(&s_best[t], pk);
                }
            }
        }
        int st0 = (b0 >= 0.5f) ? 2 : ((b0 < 0.3f) ? 0 : 1);
        int st1 = (b1 >= 0.5f) ? 2 : ((b1 < 0.3f) ? 0 : 1);
        int st2 = (b2 >= 0.5f) ? 2 : ((b2 < 0.3f) ? 0 : 1);
        s_sm[a0 + 0] = (unsigned char)(st0 * 32 + t0);
        s_sm[a0 + 1] = (unsigned char)(st1 * 32 + t1);
        s_sm[a0 + 2] = (unsigned char)(st2 * 32 + t2);
    }
    __syncthreads();

    // ---------------- Phase 2: forced matches (sequential, last-write-wins) ----
    if (tid == 0) {
        for (int t = 0; t < NT; t++) {
            unsigned long long v = s_best[t];
            unsigned int a = (v == 0ull) ? 0u : ~(unsigned int)(v & 0xFFFFFFFFull);
            s_sm[a] = (unsigned char)(2 * 32 + t);
        }
    }
    __syncthreads();

    // ---------------- Phase 3: per-anchor losses (no transcendentals for negs) --
    float sb = 0.f, sce = 0.f, sl1 = 0.f;
    int np = 0, nn = 0;
    const float* pim = pred + (size_t)b * 24 * HW;

    for (int cell = tid; cell < HW; cell += TB) {
#pragma unroll
        for (int k = 0; k < 3; k++) {
            int a = cell * 3 + k;
            const float* pb = pim + k * 8 * HW + cell;
            float obj = __ldg(pb + 4 * HW);
            unsigned char v = s_sm[a];
            int state = v >> 5;
            int t = v & 31;
            unsigned key = 0u;
            if (state == 0) { key = key_xform(obj); nn++; }
            s_keys[a] = key;
            if (state == 2) {
                np++;
                sb += fmaxf(obj, 0.f) - obj + log1pf(expf(-fabsf(obj)));  // y=1 bce
                float c0v = __ldg(pb + 5 * HW);
                float c1v = __ldg(pb + 6 * HW);
                float c2v = __ldg(pb + 7 * HW);
                float mx = fmaxf(c0v, fmaxf(c1v, c2v));
                float lse = mx + logf(expf(c0v - mx) + expf(c1v - mx) + expf(c2v - mx));
                int lab = s_tlab[t] - 1;
                float ct = (lab == 0) ? c0v : ((lab == 1) ? c1v : c2v);
                sce += lse - ct;
                int x = cell % H, y = cell / H;
                float cx = ((float)x + 0.5f) * stride;
                float cy = ((float)y + 0.5f) * stride;
                float hw = (k == 0) ? stride : ((k == 1) ? 1.25f * stride : 1.5f * stride);
                float aw = 2.f * hw;
                float4 tb = s_tb4[t];
                float gw = tb.z - tb.x, gh = tb.w - tb.y;
                float gcx = (tb.x + tb.z) * 0.5f, gcy = (tb.y + tb.w) * 0.5f;
                float td0 = (gcx - cx) / aw;
                float td1 = (gcy - cy) / aw;
                float td2 = logf(gw / aw);
                float td3 = logf(gh / aw);
                float d;
                d = fabsf(__ldg(pb + 0 * HW) - td0); sl1 += (d < 1.f) ? 0.5f * d * d : d - 0.5f;
                d = fabsf(__ldg(pb + 1 * HW) - td1); sl1 += (d < 1.f) ? 0.5f * d * d : d - 0.5f;
                d = fabsf(__ldg(pb + 2 * HW) - td2); sl1 += (d < 1.f) ? 0.5f * d * d : d - 0.5f;
                d = fabsf(__ldg(pb + 3 * HW) - td3); sl1 += (d < 1.f) ? 0.5f * d * d : d - 0.5f;
            }
        }
    }
    __syncthreads();

    float sb_t  = blk_sum_f(sb,  s_wred, tid);
    float sce_t = blk_sum_f(sce, s_wred, tid);
    float sl1_t = blk_sum_f(sl1, s_wred, tid);
    int   np_t  = blk_sum_i(np,  s_iwred, tid);
    int   nn_t  = blk_sum_i(nn,  s_iwred, tid);
    if (tid == 0) {
        s_f[0] = sb_t; s_f[1] = sce_t; s_f[2] = sl1_t;
        s_i[0] = np_t; s_i[1] = nn_t;
    }
    __syncthreads();

    const int num_pos = s_i[0];
    const int num_neg = s_i[1];
    int need = 3 * num_pos;
    if (need > num_neg) need = num_neg;

    // ---------------- Phase 4: radix-select top-`need` negative keys ------------
    float sum_sel = 0.f;
    if (need > 0) {
        if (tid == 0) { s_u[0] = 0u; s_i[2] = need; }
        __syncthreads();
#pragma unroll
        for (int pass = 0; pass < 4; pass++) {
            unsigned pfx = s_u[0];
            unsigned kk = (unsigned)s_i[2];
            if (tid < 256) s_hist[tid] = 0u;
            __syncthreads();
            int shift = 24 - 8 * pass;
            unsigned hi_mask = (pass == 0) ? 0u : (0xFFFFFFFFu << (shift + 8));
            for (int a2 = tid; a2 < A; a2 += TB) {
                unsigned key = s_keys[a2];
                if ((key & hi_mask) == pfx)
                    atomicAdd(&s_hist[(key >> shift) & 255], 1u);
            }
            __syncthreads();
            // parallel suffix-cumulative select over 256 bins (descending d)
            unsigned c = 0, incl = 0; int d = 0;
            if (tid < 256) {
                d = 255 - tid;             // tid order = descending bin order
                c = s_hist[d];
                unsigned lane = tid & 31;
                incl = c;
#pragma unroll
                for (int o = 1; o < 32; o <<= 1) {
                    unsigned n = __shfl_up_sync(0xffffffffu, incl, o);
                    if (lane >= o) incl += n;
                }
                if (lane == 31) s_ws[tid >> 5] = incl;
            }
            __syncthreads();
            if (tid < 256) {
                unsigned e = incl - c;     // exclusive within warp
                int w = tid >> 5;
                for (int i = 0; i < w; i++) e += s_ws[i];
                if (e < kk && kk <= e + c) {
                    s_u[0] = pfx | ((unsigned)d << shift);
                    s_u[1] = kk - e;
                }
            }
            __syncthreads();
            if (tid == 0) s_i[2] = (int)s_u[1];
            __syncthreads();
        }
        unsigned kth = s_u[0];
        float sg = 0.f; int cg = 0;
        for (int a2 = tid; a2 < A; a2 += TB) {
            unsigned key = s_keys[a2];
            if (key > kth) { sg += bce_neg(key_inv(key)); cg++; }  // bce only on selected
        }
        float sg_t = blk_sum_f(sg, s_wred, tid);
        int   cg_t = blk_sum_i(cg, s_iwred, tid);
        if (tid == 0) sum_sel = sg_t + (float)(need - cg_t) * bce_neg(key_inv(kth));
    }

    // ---------------- Phase 5: per-image losses ----------------
    if (tid == 0) {
        int denom_obj = num_pos + need; if (denom_obj < 1) denom_obj = 1;
        int denom_cls = num_pos;        if (denom_cls < 1) denom_cls = 1;
        int denom_loc = 4 * num_pos;    if (denom_loc < 1) denom_loc = 1;
        int idx = (sc * 64 + b) * 3;
        g_partial[idx + 0] = (s_f[0] + sum_sel) / (float)denom_obj;
        g_partial[idx + 1] = s_f[1] / (float)denom_cls;
        g_partial[idx + 2] = s_f[2] / (float)denom_loc;
    }

    // ---------------- Phase 6: last block finalizes ----------------
    __threadfence();
    if (tid == 0) {
        int ticket = atomicAdd(&g_ctr, 1);
        s_last = (ticket == 191);
    }
    __syncthreads();
    if (s_last && tid < 32) {
        float o = 0.f, c = 0.f, l = 0.f;
        for (int i = tid; i < 192; i += 32) {
            o += g_partial[3 * i + 0];
            c += g_partial[3 * i + 1];
            l += g_partial[3 * i + 2];
        }
#pragma unroll
        for (int s = 16; s; s >>= 1) {
            o += __shfl_down_sync(0xffffffffu, o, s);
            c += __shfl_down_sync(0xffffffffu, c, s);
            l += __shfl_down_sync(0xffffffffu, l, s);
        }
        if (tid == 0) {
            o *= (1.f / 64.f);
            c *= (1.f / 64.f);
            l *= (1.f / 64.f);
            out[0] = o;
            out[1] = c;
            out[2] = l;
            out[3] = o + c + 2.f * l;
            g_ctr = 0;  // reset for next graph replay
        }
    }
}

extern "C" void kernel_launch(void* const* d_in, const int* in_sizes, int n_in,
                              void* d_out, int out_size) {
    const float* p1 = (const float*)d_in[0];
    const float* p2 = (const float*)d_in[1];
    const float* p3 = (const float*)d_in[2];
    const float* tb = (const float*)d_in[6];
    const int*   tl = (const int*)d_in[7];

    dim3 grid(64, 3);
    det_loss_kernel<<<grid, TB>>>(p1, p2, p3, tb, tl, (float*)d_out);
}